// round 15
// baseline (speedup 1.0000x reference)
#include <cuda_runtime.h>

// ---------------------------------------------------------------------------
// DensityGrid: fused opacity/caching + keep-largest-connected-component.
// ONE persistent kernel; R15: 768 blocks (3x4x96 tiles) to raise occupancy —
// R14 showed occ was capped by block count (576/148=3.9 blk/SM = 48.5%),
// not launch bounds. 768/148=5.2 blk/SM -> ~65% occ.
// Phases: A(prep+pool(nc)+speculative outputs+partials) -> barrier ->
//   fast path (g_notfull==0: every tile fully >0.01 => thresh<=0.01 => mask
//   full => speculative outputs exact): exit.
//   slow path: reduce sum -> labels -> barrier -> reduce mask (+reset
//   g_notfull) -> chase+hist+argmax -> barrier -> reduce keys -> overwrite.
// Pool runs on nc (monotone-commute with f=1-exp(-.01x)), exp once/output.
// Co-residency: __launch_bounds__(256,6) (regs<=42), smem 23.0KB*6=138KB
// <=227KB, 148*6=888>=768 -> all blocks wave-1 resident. Gating branches
// grid-uniform. All shortcuts EXACT; chases READ-ONLY + coalesced write.
// g_notfull is reset-free on the fast path (never written there).
// ---------------------------------------------------------------------------

#define Gn   96
#define G2n  (Gn * Gn)
#define G3n  (Gn * Gn * Gn)
#define NT   256
#define NQ   (G3n / 4)             /* 221184 vec4 elems     */
#define ROWQ (Gn / 4)              /* 24 vec4 per x-row     */

#define TY 4
#define TZ 3
#define HY (TY + 2)                /* 6 */
#define HZ (TZ + 2)                /* 5 */
#define YT (Gn / TY)               /* 24 y-tiles */
#define ZT (Gn / TZ)               /* 32 z-tiles */
#define NBF (YT * ZT)              /* 768 blocks; all co-resident */
#define TILEVOX (TZ * TY * Gn)     /* 1152 voxels per tile  */

// ----- scratch (device globals; partials overwritten before every read) -----
__device__ float              g_f1[G3n];        // pooled field (post exp)
__device__ unsigned int       g_lab[G3n];
__device__ unsigned int       g_cnt[G3n + 1];   // zero at load; slow path re-zeroes
__device__ float              g_psum[NBF];
__device__ unsigned int       g_pmask[NBF];
__device__ unsigned long long g_pkey[NBF];
__device__ unsigned int       g_notfull;        // 0 at load; fast path never writes
__device__ unsigned int       g_barcnt;         // self-resets at release
__device__ volatile unsigned  g_bargen;         // monotone generation

__device__ __forceinline__ float4 fmax4(float4 a, float4 b) {
    return make_float4(fmaxf(a.x, b.x), fmaxf(a.y, b.y),
                       fmaxf(a.z, b.z), fmaxf(a.w, b.w));
}

// ----- grid barrier (all NBF blocks co-resident by construction) ------------
__device__ __forceinline__ void grid_barrier() {
    __syncthreads();
    if (threadIdx.x == 0) {
        __threadfence();
        unsigned gen = g_bargen;
        if (atomicAdd(&g_barcnt, 1u) == (unsigned)NBF - 1u) {
            g_barcnt = 0u;
            __threadfence();
            g_bargen = gen + 1u;
        } else {
            while (g_bargen == gen) { }
        }
        __threadfence();
    }
    __syncthreads();
}

// ----- scalar fallback: max masked 26-neighbor (descending-index probes) ----
__device__ __forceinline__ unsigned probe_parent(int i, float t) {
    int x = i % Gn, y = (i / Gn) % Gn, z = i / G2n;
    #pragma unroll
    for (int dz = 1; dz >= -1; --dz) {
        int zz = z + dz;
        if ((unsigned)zz >= (unsigned)Gn) continue;
        #pragma unroll
        for (int dy = 1; dy >= -1; --dy) {
            int yy = y + dy;
            if ((unsigned)yy >= (unsigned)Gn) continue;
            #pragma unroll
            for (int dx = 1; dx >= -1; --dx) {
                if (dz == 0 && dy == 0 && dx == 0)
                    return (unsigned)(i + 1);          // self is max
                int xx = x + dx;
                if ((unsigned)xx >= (unsigned)Gn) continue;
                int j = (zz * Gn + yy) * Gn + xx;
                if (g_f1[j] > t) return (unsigned)(j + 1);
            }
        }
    }
    return (unsigned)(i + 1);
}

// ----- read-only find-root chase ---------------------------------------------
__device__ __forceinline__ unsigned find_root(unsigned L) {
    if (!L) return 0u;
    unsigned w = L - 1u;
    for (;;) {
        unsigned p = g_lab[w];
        if (p == w + 1u) return p;
        w = p - 1u;
    }
}

// ============================================================================
__global__ __launch_bounds__(NT, 6)
void k_all(const float4* __restrict__ dens,
           const float4* __restrict__ cach,
           const int4*   __restrict__ oldf,
           const int*    __restrict__ step,
           float4*       __restrict__ out) {
    __shared__ float fA[HZ * HY * Gn];     /* 11520 B */
    __shared__ float fB[HZ * HY * Gn];     /* 11520 B */
    __shared__ float    shf[NT / 32];
    __shared__ unsigned shu[NT / 32];
    __shared__ float    bc_f;
    __shared__ unsigned bc_u;
    __shared__ unsigned long long bc_k;

    int b = blockIdx.x;
    int t = threadIdx.x;
    int lane = t & 31, wid = t >> 5;
    int st = step[0];

    // ===== phase A: prep + pool(nc) + speculative outputs + partials =====
    {
        int zb = b / YT, yb = b % YT;
        // halo load: nc into smem (NO exp); interior writes od/nc/spec outputs
        for (int s = t; s < HZ * HY * ROWQ; s += NT) {
            int zi = s / (HY * ROWQ), rem = s % (HY * ROWQ);
            int yi = rem / ROWQ, xq = rem % ROWQ;
            int gz = zb * TZ - 1 + zi, gy = yb * TY - 1 + yi;
            float4 nc = make_float4(0.f, 0.f, 0.f, 0.f);
            if ((unsigned)gz < (unsigned)Gn && (unsigned)gy < (unsigned)Gn) {
                int q = (gz * Gn + gy) * ROWQ + xq;
                float4 d = dens[q], c = cach[q];
                d.x = fmaxf(d.x, 0.f); d.y = fmaxf(d.y, 0.f);
                d.z = fmaxf(d.z, 0.f); d.w = fmaxf(d.w, 0.f);
                nc = make_float4(fmaxf(0.8f * c.x, d.x), fmaxf(0.8f * c.y, d.y),
                                 fmaxf(0.8f * c.z, d.z), fmaxf(0.8f * c.w, d.w));
                if (zi >= 1 && zi <= TZ && yi >= 1 && yi <= TY) {
                    float4 od = make_float4(
                        1.f - __expf(-0.01f * d.x), 1.f - __expf(-0.01f * d.y),
                        1.f - __expf(-0.01f * d.z), 1.f - __expf(-0.01f * d.w));
                    out[q]          = od;   // out_density
                    out[3 * NQ + q] = nc;   // new_cached
                    // speculative full-mask outputs (exact when mask full)
                    out[2 * NQ + q] = make_float4(1.f, 1.f, 1.f, 1.f);
                    float4 vd;
                    if (st < 500) {
                        vd = make_float4(1.f, 1.f, 1.f, 1.f);
                    } else {
                        int4 o = oldf[q];
                        vd = make_float4(o.x ? 1.f : 0.f, o.y ? 1.f : 0.f,
                                         o.z ? 1.f : 0.f, o.w ? 1.f : 0.f);
                    }
                    out[NQ + q] = vd;       // valid
                }
            }
            ((float4*)fA)[s] = nc;
        }
        __syncthreads();

        // x-pool fA -> fB (window 3, zero pad at row ends)
        for (int s = t; s < HZ * HY * ROWQ; s += NT) {
            int xq = s % ROWQ;
            float4 v = ((const float4*)fA)[s];
            int base = s * 4;
            float l = (xq > 0)        ? fA[base - 1] : 0.f;
            float r = (xq < ROWQ - 1) ? fA[base + 4] : 0.f;
            float4 o;
            o.x = fmaxf(fmaxf(l,   v.x), v.y);
            o.y = fmaxf(fmaxf(v.x, v.y), v.z);
            o.z = fmaxf(fmaxf(v.y, v.z), v.w);
            o.w = fmaxf(fmaxf(v.z, v.w), r);
            ((float4*)fB)[s] = o;
        }
        __syncthreads();

        // y-pool fB -> fA ([HZ][TY][96])
        for (int s = t; s < HZ * TY * ROWQ; s += NT) {
            int zi = s / (TY * ROWQ), rem = s % (TY * ROWQ);
            int yo = rem / ROWQ, xq = rem % ROWQ;
            const float4* src = (const float4*)fB;
            float4 v =   src[(zi * HY + yo)     * ROWQ + xq];
            v = fmax4(v, src[(zi * HY + yo + 1) * ROWQ + xq]);
            v = fmax4(v, src[(zi * HY + yo + 2) * ROWQ + xq]);
            ((float4*)fA)[s] = v;
        }
        __syncthreads();

        // z-pool fA -> f = 1-exp(-.01*poolednc) -> g_f1; partial sum + c01
        float ssum = 0.f;
        unsigned c01 = 0u;
        for (int s = t; s < TZ * TY * ROWQ; s += NT) {
            int zo = s / (TY * ROWQ), rem = s % (TY * ROWQ);
            int yo = rem / ROWQ, xq = rem % ROWQ;
            const float4* src = (const float4*)fA;
            float4 v =   src[((zo)     * TY + yo) * ROWQ + xq];
            v = fmax4(v, src[((zo + 1) * TY + yo) * ROWQ + xq]);
            v = fmax4(v, src[((zo + 2) * TY + yo) * ROWQ + xq]);
            float4 f = make_float4(1.f - __expf(-0.01f * v.x),
                                   1.f - __expf(-0.01f * v.y),
                                   1.f - __expf(-0.01f * v.z),
                                   1.f - __expf(-0.01f * v.w));
            int gz = zb * TZ + zo, gy = yb * TY + yo;
            ((float4*)g_f1)[(gz * Gn + gy) * ROWQ + xq] = f;
            ssum += (f.x + f.y) + (f.z + f.w);
            c01  += (f.x > 0.01f ? 1u : 0u) + (f.y > 0.01f ? 1u : 0u) +
                    (f.z > 0.01f ? 1u : 0u) + (f.w > 0.01f ? 1u : 0u);
        }
        #pragma unroll
        for (int off = 16; off > 0; off >>= 1) {
            ssum += __shfl_down_sync(0xffffffffu, ssum, off);
            c01  += __shfl_down_sync(0xffffffffu, c01,  off);
        }
        if (lane == 0) { shf[wid] = ssum; shu[wid] = c01; }
        __syncthreads();
        if (t == 0) {
            ssum = 0.f; c01 = 0u;
            #pragma unroll
            for (int w = 0; w < NT / 32; ++w) { ssum += shf[w]; c01 += shu[w]; }
            g_psum[b] = ssum;
            if (c01 != (unsigned)TILEVOX) atomicAdd(&g_notfull, 1u);
        }
    }

    grid_barrier();

    // FAST PATH: every tile fully >0.01 -> thresh<=0.01 -> mask full ->
    // speculative outputs already exact. (g_notfull untouched: reset-free.)
    if (g_notfull == 0u) return;        // grid-uniform

    // ======================= slow path =======================
    // reduce sum partials (every block identically; deterministic)
    float sumv = 0.f;
    for (int i = t; i < NBF; i += NT) sumv += g_psum[i];
    #pragma unroll
    for (int off = 16; off > 0; off >>= 1)
        sumv += __shfl_down_sync(0xffffffffu, sumv, off);
    __syncthreads();
    if (lane == 0) shf[wid] = sumv;
    __syncthreads();
    if (t == 0) {
        sumv = 0.f;
        #pragma unroll
        for (int w = 0; w < NT / 32; ++w) sumv += shf[w];
        bc_f = sumv;
    }
    __syncthreads();
    sumv = bc_f;

    // phase 1: exact hill-climb labels + mask count
    {
        float th = fminf(sumv * (1.f / (float)G3n), 0.01f);
        unsigned cmask = 0u;
        for (int q = b * NT + t; q < NQ; q += NBF * NT) {
            int xq = q % ROWQ, rowi = q / ROWQ;
            int y = rowi % Gn, z = rowi / Gn;
            float4 f = ((const float4*)g_f1)[q];
            int i0 = q * 4;
            uint4 L = make_uint4(0u, 0u, 0u, 0u);
            if (z < Gn - 1 && y < Gn - 1 && xq < ROWQ - 1) {
                int jb = i0 + G2n + Gn;                 // (z+1,y+1,x0)
                float4 pv = ((const float4*)g_f1)[jb >> 2];
                float  pe = g_f1[jb + 4];
                if (f.x > th) L.x = (pv.y > th) ? (unsigned)(jb + 2) : probe_parent(i0 + 0, th);
                if (f.y > th) L.y = (pv.z > th) ? (unsigned)(jb + 3) : probe_parent(i0 + 1, th);
                if (f.z > th) L.z = (pv.w > th) ? (unsigned)(jb + 4) : probe_parent(i0 + 2, th);
                if (f.w > th) L.w = (pe   > th) ? (unsigned)(jb + 5) : probe_parent(i0 + 3, th);
            } else {
                if (f.x > th) L.x = probe_parent(i0 + 0, th);
                if (f.y > th) L.y = probe_parent(i0 + 1, th);
                if (f.z > th) L.z = probe_parent(i0 + 2, th);
                if (f.w > th) L.w = probe_parent(i0 + 3, th);
            }
            ((uint4*)g_lab)[q] = L;
            cmask += (L.x ? 1u : 0u) + (L.y ? 1u : 0u) +
                     (L.z ? 1u : 0u) + (L.w ? 1u : 0u);
        }
        #pragma unroll
        for (int off = 16; off > 0; off >>= 1)
            cmask += __shfl_down_sync(0xffffffffu, cmask, off);
        __syncthreads();
        if (lane == 0) shu[wid] = cmask;
        __syncthreads();
        if (t == 0) {
            cmask = 0u;
            #pragma unroll
            for (int w = 0; w < NT / 32; ++w) cmask += shu[w];
            g_pmask[b] = cmask;
        }
    }

    grid_barrier();

    // all reads of g_notfull are done (pre-barrier); reset for next replay
    if (b == 0 && t == 0) g_notfull = 0u;

    // reduce mask partials
    unsigned nmask = 0u;
    for (int i = t; i < NBF; i += NT) nmask += g_pmask[i];
    #pragma unroll
    for (int off = 16; off > 0; off >>= 1)
        nmask += __shfl_down_sync(0xffffffffu, nmask, off);
    __syncthreads();
    if (lane == 0) shu[wid] = nmask;
    __syncthreads();
    if (t == 0) {
        nmask = 0u;
        #pragma unroll
        for (int w = 0; w < NT / 32; ++w) nmask += shu[w];
        bc_u = nmask;
    }
    __syncthreads();
    nmask = bc_u;

    if (nmask == (unsigned)G3n) return; // mask full: speculative outputs exact

    // phase 2: chase + hist + per-block argmax
    {
        __shared__ unsigned long long blockKey;
        if (t == 0) blockKey = 0ull;
        __syncthreads();
        for (int q = b * NT + t; q < NQ; q += NBF * NT) {
            uint4 L = ((const uint4*)g_lab)[q];
            L.x = find_root(L.x); L.y = find_root(L.y);
            L.z = find_root(L.z); L.w = find_root(L.w);
            ((uint4*)g_lab)[q] = L;
            unsigned ls[4] = {L.x, L.y, L.z, L.w};
            #pragma unroll
            for (int k = 0; k < 4; ++k) {
                unsigned Lk = ls[k];
                unsigned peers = __match_any_sync(0xffffffffu, Lk);
                if (Lk && lane == (__ffs(peers) - 1)) {
                    unsigned n   = (unsigned)__popc(peers);
                    unsigned old = atomicAdd(&g_cnt[Lk], n);
                    unsigned long long key =
                        ((unsigned long long)(old + n) << 32) |
                        (unsigned long long)(0xFFFFFFFFu - Lk);
                    atomicMax(&blockKey, key);
                }
            }
        }
        __syncthreads();
        if (t == 0) g_pkey[b] = blockKey;
    }

    grid_barrier();

    // reduce keys
    unsigned long long kmax = 0ull;
    for (int i = t; i < NBF; i += NT) {
        unsigned long long kk = g_pkey[i];
        kmax = (kk > kmax) ? kk : kmax;
    }
    #pragma unroll
    for (int off = 16; off > 0; off >>= 1) {
        unsigned long long o = __shfl_down_sync(0xffffffffu, kmax, off);
        kmax = (o > kmax) ? o : kmax;
    }
    __shared__ unsigned long long shk[NT / 32];
    if (lane == 0) shk[wid] = kmax;
    __syncthreads();
    if (t == 0) {
        kmax = 0ull;
        #pragma unroll
        for (int w = 0; w < NT / 32; ++w)
            kmax = (shk[w] > kmax) ? shk[w] : kmax;
        bc_k = kmax;
    }
    __syncthreads();
    unsigned win = 0xFFFFFFFFu - (unsigned)(bc_k & 0xFFFFFFFFull);

    // overwrite speculative outputs with true component compare
    for (int q = b * NT + t; q < NQ; q += NBF * NT) {
        uint4 L = ((const uint4*)g_lab)[q];
        float4 nf = make_float4(L.x == win ? 1.f : 0.f, L.y == win ? 1.f : 0.f,
                                L.z == win ? 1.f : 0.f, L.w == win ? 1.f : 0.f);
        out[2 * NQ + q] = nf;                 // new_field
        if (st < 500) out[NQ + q] = nf;       // valid (st>=500 already correct)
        ((uint4*)g_cnt)[q] = make_uint4(0u, 0u, 0u, 0u);  // re-zero hist
    }
    if (b == 0 && t == 0) g_cnt[G3n] = 0u;
}

// ---------------------------------------------------------------------------
extern "C" void kernel_launch(void* const* d_in, const int* in_sizes, int n_in,
                              void* d_out, int out_size) {
    const float4* dens = (const float4*)d_in[0];
    const float4* cach = (const float4*)d_in[1];
    const int4*   oldf = (const int4*)d_in[2];
    const int*    step = (const int*)d_in[3];
    float4*       out  = (float4*)d_out;

    k_all<<<NBF, NT>>>(dens, cach, oldf, step, out);
}

// round 16
// speedup vs baseline: 1.3901x; 1.3901x over previous
#include <cuda_runtime.h>

// ---------------------------------------------------------------------------
// DensityGrid: fused opacity/caching + keep-largest-connected-component.
// ONE persistent kernel. R16: the FAST PATH has NO pooling at all.
// Gate certificate: with C=1.01, f(C)=1-exp(-.0101)=0.01005>0.01>=thresh,
// and pooled_nc >= any 27-neighborhood nc, so a voxel's mask bit is PROVEN
// if any 3^3-neighbor has nc > C. Phase A streams: nc/od/speculative
// outputs; voxels with nc<=C (~1e-4 of data) probe their neighborhood and
// mark g_notfull only if ALL 27 are low. Fast path = streaming + 1 barrier.
// Slow path (any unproven voxel): rebuild nc from out[3G^3..] (fenced
// barrier makes it visible), smem-tile pool -> g_f1 + sum partials ->
// barrier -> threshold -> exact hill-climb labels -> barrier (+reset
// g_notfull) -> mask count (full => speculative outputs exact => exit) ->
// chase+hist+argmax -> barrier -> reduce keys -> overwrite outputs.
// Co-residency: __launch_bounds__(256,6) (regs<=42), smem 23KB*6=138KB
// <=227KB, 148*6=888>=768 blocks -> all wave-1 resident; barrier safe.
// Gating branches grid-uniform. All shortcuts EXACT; chases READ-ONLY.
// g_notfull: 0 at load, never written on fast path -> reset-free there;
// slow path resets it behind a later barrier.
// ---------------------------------------------------------------------------

#define Gn   96
#define G2n  (Gn * Gn)
#define G3n  (Gn * Gn * Gn)
#define NT   256
#define NQ   (G3n / 4)             /* 221184 vec4 elems     */
#define ROWQ (Gn / 4)              /* 24 vec4 per x-row     */

#define TY 4
#define TZ 3
#define HY (TY + 2)                /* 6 */
#define HZ (TZ + 2)                /* 5 */
#define YT (Gn / TY)               /* 24 y-tiles */
#define ZT (Gn / TZ)               /* 32 z-tiles */
#define NBF (YT * ZT)              /* 768 blocks; all co-resident */

#define NCLOW 1.01f                /* f(1.01)=0.010049 > 0.01 with margin */

// ----- scratch (device globals; partials overwritten before every read) -----
__device__ float              g_f1[G3n];        // pooled field (slow path only)
__device__ unsigned int       g_lab[G3n];
__device__ unsigned int       g_cnt[G3n + 1];   // zero at load; slow path re-zeroes
__device__ float              g_psum[NBF];
__device__ unsigned int       g_pmask[NBF];
__device__ unsigned long long g_pkey[NBF];
__device__ unsigned int       g_notfull;        // 0 at load; fast path never writes
__device__ unsigned int       g_barcnt;         // self-resets at release
__device__ volatile unsigned  g_bargen;         // monotone generation

__device__ __forceinline__ float4 fmax4(float4 a, float4 b) {
    return make_float4(fmaxf(a.x, b.x), fmaxf(a.y, b.y),
                       fmaxf(a.z, b.z), fmaxf(a.w, b.w));
}

// ----- grid barrier (all NBF blocks co-resident by construction) ------------
__device__ __forceinline__ void grid_barrier() {
    __syncthreads();
    if (threadIdx.x == 0) {
        __threadfence();
        unsigned gen = g_bargen;
        if (atomicAdd(&g_barcnt, 1u) == (unsigned)NBF - 1u) {
            g_barcnt = 0u;
            __threadfence();
            g_bargen = gen + 1u;
        } else {
            while (g_bargen == gen) { }
        }
        __threadfence();
    }
    __syncthreads();
}

// ----- rare probe: does ANY in-bounds 3^3 neighbor have nc > NCLOW? ----------
__device__ __forceinline__ bool nbr_above(int i, const float* __restrict__ densf,
                                          const float* __restrict__ cachf) {
    int x = i % Gn, y = (i / Gn) % Gn, z = i / G2n;
    for (int dz = -1; dz <= 1; ++dz) {
        int zz = z + dz;
        if ((unsigned)zz >= (unsigned)Gn) continue;
        for (int dy = -1; dy <= 1; ++dy) {
            int yy = y + dy;
            if ((unsigned)yy >= (unsigned)Gn) continue;
            for (int dx = -1; dx <= 1; ++dx) {
                int xx = x + dx;
                if ((unsigned)xx >= (unsigned)Gn) continue;
                int j = (zz * Gn + yy) * Gn + xx;
                float nc = fmaxf(0.8f * cachf[j], fmaxf(densf[j], 0.f));
                if (nc > NCLOW) return true;
            }
        }
    }
    return false;
}

// ----- scalar fallback: max masked 26-neighbor (descending-index probes) ----
__device__ __forceinline__ unsigned probe_parent(int i, float t) {
    int x = i % Gn, y = (i / Gn) % Gn, z = i / G2n;
    #pragma unroll
    for (int dz = 1; dz >= -1; --dz) {
        int zz = z + dz;
        if ((unsigned)zz >= (unsigned)Gn) continue;
        #pragma unroll
        for (int dy = 1; dy >= -1; --dy) {
            int yy = y + dy;
            if ((unsigned)yy >= (unsigned)Gn) continue;
            #pragma unroll
            for (int dx = 1; dx >= -1; --dx) {
                if (dz == 0 && dy == 0 && dx == 0)
                    return (unsigned)(i + 1);          // self is max
                int xx = x + dx;
                if ((unsigned)xx >= (unsigned)Gn) continue;
                int j = (zz * Gn + yy) * Gn + xx;
                if (g_f1[j] > t) return (unsigned)(j + 1);
            }
        }
    }
    return (unsigned)(i + 1);
}

// ----- read-only find-root chase ---------------------------------------------
__device__ __forceinline__ unsigned find_root(unsigned L) {
    if (!L) return 0u;
    unsigned w = L - 1u;
    for (;;) {
        unsigned p = g_lab[w];
        if (p == w + 1u) return p;
        w = p - 1u;
    }
}

// ============================================================================
__global__ __launch_bounds__(NT, 6)
void k_all(const float4* __restrict__ dens,
           const float4* __restrict__ cach,
           const int4*   __restrict__ oldf,
           const int*    __restrict__ step,
           float4*       __restrict__ out) {
    __shared__ float fA[HZ * HY * Gn];     /* 11520 B (slow path pool) */
    __shared__ float fB[HZ * HY * Gn];     /* 11520 B */
    __shared__ float    shf[NT / 32];
    __shared__ unsigned shu[NT / 32];
    __shared__ float    bc_f;
    __shared__ unsigned bc_u;
    __shared__ unsigned long long bc_k;

    int b = blockIdx.x;
    int t = threadIdx.x;
    int lane = t & 31, wid = t >> 5;
    int st = step[0];
    const float* densf = (const float*)dens;
    const float* cachf = (const float*)cach;

    // ===== phase A: PURE STREAMING (no pool, no smem, no syncthreads) =====
    unsigned bad = 0u;
    for (int q = b * NT + t; q < NQ; q += NBF * NT) {
        float4 d = dens[q], c = cach[q];
        d.x = fmaxf(d.x, 0.f); d.y = fmaxf(d.y, 0.f);
        d.z = fmaxf(d.z, 0.f); d.w = fmaxf(d.w, 0.f);
        float4 nc = make_float4(fmaxf(0.8f * c.x, d.x), fmaxf(0.8f * c.y, d.y),
                                fmaxf(0.8f * c.z, d.z), fmaxf(0.8f * c.w, d.w));
        float4 od = make_float4(
            1.f - __expf(-0.01f * d.x), 1.f - __expf(-0.01f * d.y),
            1.f - __expf(-0.01f * d.z), 1.f - __expf(-0.01f * d.w));
        out[q]          = od;                         // out_density
        out[3 * NQ + q] = nc;                         // new_cached
        out[2 * NQ + q] = make_float4(1.f, 1.f, 1.f, 1.f); // spec new_field
        float4 vd;
        if (st < 500) {
            vd = make_float4(1.f, 1.f, 1.f, 1.f);
        } else {
            int4 o = oldf[q];
            vd = make_float4(o.x ? 1.f : 0.f, o.y ? 1.f : 0.f,
                             o.z ? 1.f : 0.f, o.w ? 1.f : 0.f);
        }
        out[NQ + q] = vd;                             // spec valid

        // rare certificate check: any voxel with nc<=C probes its 3^3 nbrs
        if (nc.x <= NCLOW || nc.y <= NCLOW || nc.z <= NCLOW || nc.w <= NCLOW) {
            int i0 = q * 4;
            if (nc.x <= NCLOW && !nbr_above(i0 + 0, densf, cachf)) bad++;
            if (nc.y <= NCLOW && !nbr_above(i0 + 1, densf, cachf)) bad++;
            if (nc.z <= NCLOW && !nbr_above(i0 + 2, densf, cachf)) bad++;
            if (nc.w <= NCLOW && !nbr_above(i0 + 3, densf, cachf)) bad++;
        }
    }
    if (bad) atomicAdd(&g_notfull, bad);

    grid_barrier();

    // FAST PATH: every voxel certified (pooled f > 0.01 >= thresh) -> mask
    // full -> speculative outputs already exact. g_notfull untouched.
    if (g_notfull == 0u) return;        // grid-uniform

    // ======================= slow path =======================
    // S0: rebuild pooled field from nc (already in out[3NQ..]) on tile b
    const float4* ncsrc = out + 3 * NQ;
    {
        int zb = b / YT, yb = b % YT;
        for (int s = t; s < HZ * HY * ROWQ; s += NT) {
            int zi = s / (HY * ROWQ), rem = s % (HY * ROWQ);
            int yi = rem / ROWQ, xq = rem % ROWQ;
            int gz = zb * TZ - 1 + zi, gy = yb * TY - 1 + yi;
            float4 nc = make_float4(0.f, 0.f, 0.f, 0.f);
            if ((unsigned)gz < (unsigned)Gn && (unsigned)gy < (unsigned)Gn)
                nc = ncsrc[(gz * Gn + gy) * ROWQ + xq];
            ((float4*)fA)[s] = nc;
        }
        __syncthreads();

        // x-pool fA -> fB
        for (int s = t; s < HZ * HY * ROWQ; s += NT) {
            int xq = s % ROWQ;
            float4 v = ((const float4*)fA)[s];
            int base = s * 4;
            float l = (xq > 0)        ? fA[base - 1] : 0.f;
            float r = (xq < ROWQ - 1) ? fA[base + 4] : 0.f;
            float4 o;
            o.x = fmaxf(fmaxf(l,   v.x), v.y);
            o.y = fmaxf(fmaxf(v.x, v.y), v.z);
            o.z = fmaxf(fmaxf(v.y, v.z), v.w);
            o.w = fmaxf(fmaxf(v.z, v.w), r);
            ((float4*)fB)[s] = o;
        }
        __syncthreads();

        // y-pool fB -> fA ([HZ][TY][96])
        for (int s = t; s < HZ * TY * ROWQ; s += NT) {
            int zi = s / (TY * ROWQ), rem = s % (TY * ROWQ);
            int yo = rem / ROWQ, xq = rem % ROWQ;
            const float4* src = (const float4*)fB;
            float4 v =   src[(zi * HY + yo)     * ROWQ + xq];
            v = fmax4(v, src[(zi * HY + yo + 1) * ROWQ + xq]);
            v = fmax4(v, src[(zi * HY + yo + 2) * ROWQ + xq]);
            ((float4*)fA)[s] = v;
        }
        __syncthreads();

        // z-pool fA -> f = 1-exp(-.01*poolednc) -> g_f1; partial sum
        float ssum = 0.f;
        for (int s = t; s < TZ * TY * ROWQ; s += NT) {
            int zo = s / (TY * ROWQ), rem = s % (TY * ROWQ);
            int yo = rem / ROWQ, xq = rem % ROWQ;
            const float4* src = (const float4*)fA;
            float4 v =   src[((zo)     * TY + yo) * ROWQ + xq];
            v = fmax4(v, src[((zo + 1) * TY + yo) * ROWQ + xq]);
            v = fmax4(v, src[((zo + 2) * TY + yo) * ROWQ + xq]);
            float4 f = make_float4(1.f - __expf(-0.01f * v.x),
                                   1.f - __expf(-0.01f * v.y),
                                   1.f - __expf(-0.01f * v.z),
                                   1.f - __expf(-0.01f * v.w));
            int gz = zb * TZ + zo, gy = yb * TY + yo;
            ((float4*)g_f1)[(gz * Gn + gy) * ROWQ + xq] = f;
            ssum += (f.x + f.y) + (f.z + f.w);
        }
        #pragma unroll
        for (int off = 16; off > 0; off >>= 1)
            ssum += __shfl_down_sync(0xffffffffu, ssum, off);
        if (lane == 0) shf[wid] = ssum;
        __syncthreads();
        if (t == 0) {
            ssum = 0.f;
            #pragma unroll
            for (int w = 0; w < NT / 32; ++w) ssum += shf[w];
            g_psum[b] = ssum;
        }
    }

    grid_barrier();

    // reduce sum partials (every block identically; deterministic)
    float sumv = 0.f;
    for (int i = t; i < NBF; i += NT) sumv += g_psum[i];
    #pragma unroll
    for (int off = 16; off > 0; off >>= 1)
        sumv += __shfl_down_sync(0xffffffffu, sumv, off);
    __syncthreads();
    if (lane == 0) shf[wid] = sumv;
    __syncthreads();
    if (t == 0) {
        sumv = 0.f;
        #pragma unroll
        for (int w = 0; w < NT / 32; ++w) sumv += shf[w];
        bc_f = sumv;
    }
    __syncthreads();
    sumv = bc_f;

    // phase 1: exact hill-climb labels + mask count
    {
        float th = fminf(sumv * (1.f / (float)G3n), 0.01f);
        unsigned cmask = 0u;
        for (int q = b * NT + t; q < NQ; q += NBF * NT) {
            int xq = q % ROWQ, rowi = q / ROWQ;
            int y = rowi % Gn, z = rowi / Gn;
            float4 f = ((const float4*)g_f1)[q];
            int i0 = q * 4;
            uint4 L = make_uint4(0u, 0u, 0u, 0u);
            if (z < Gn - 1 && y < Gn - 1 && xq < ROWQ - 1) {
                int jb = i0 + G2n + Gn;                 // (z+1,y+1,x0)
                float4 pv = ((const float4*)g_f1)[jb >> 2];
                float  pe = g_f1[jb + 4];
                if (f.x > th) L.x = (pv.y > th) ? (unsigned)(jb + 2) : probe_parent(i0 + 0, th);
                if (f.y > th) L.y = (pv.z > th) ? (unsigned)(jb + 3) : probe_parent(i0 + 1, th);
                if (f.z > th) L.z = (pv.w > th) ? (unsigned)(jb + 4) : probe_parent(i0 + 2, th);
                if (f.w > th) L.w = (pe   > th) ? (unsigned)(jb + 5) : probe_parent(i0 + 3, th);
            } else {
                if (f.x > th) L.x = probe_parent(i0 + 0, th);
                if (f.y > th) L.y = probe_parent(i0 + 1, th);
                if (f.z > th) L.z = probe_parent(i0 + 2, th);
                if (f.w > th) L.w = probe_parent(i0 + 3, th);
            }
            ((uint4*)g_lab)[q] = L;
            cmask += (L.x ? 1u : 0u) + (L.y ? 1u : 0u) +
                     (L.z ? 1u : 0u) + (L.w ? 1u : 0u);
        }
        #pragma unroll
        for (int off = 16; off > 0; off >>= 1)
            cmask += __shfl_down_sync(0xffffffffu, cmask, off);
        __syncthreads();
        if (lane == 0) shu[wid] = cmask;
        __syncthreads();
        if (t == 0) {
            cmask = 0u;
            #pragma unroll
            for (int w = 0; w < NT / 32; ++w) cmask += shu[w];
            g_pmask[b] = cmask;
        }
    }

    grid_barrier();

    // all reads of g_notfull are long done; reset for next replay
    if (b == 0 && t == 0) g_notfull = 0u;

    // reduce mask partials
    unsigned nmask = 0u;
    for (int i = t; i < NBF; i += NT) nmask += g_pmask[i];
    #pragma unroll
    for (int off = 16; off > 0; off >>= 1)
        nmask += __shfl_down_sync(0xffffffffu, nmask, off);
    __syncthreads();
    if (lane == 0) shu[wid] = nmask;
    __syncthreads();
    if (t == 0) {
        nmask = 0u;
        #pragma unroll
        for (int w = 0; w < NT / 32; ++w) nmask += shu[w];
        bc_u = nmask;
    }
    __syncthreads();
    nmask = bc_u;

    if (nmask == (unsigned)G3n) return; // mask full: speculative outputs exact

    // phase 2: chase + hist + per-block argmax
    {
        __shared__ unsigned long long blockKey;
        if (t == 0) blockKey = 0ull;
        __syncthreads();
        for (int q = b * NT + t; q < NQ; q += NBF * NT) {
            uint4 L = ((const uint4*)g_lab)[q];
            L.x = find_root(L.x); L.y = find_root(L.y);
            L.z = find_root(L.z); L.w = find_root(L.w);
            ((uint4*)g_lab)[q] = L;
            unsigned ls[4] = {L.x, L.y, L.z, L.w};
            #pragma unroll
            for (int k = 0; k < 4; ++k) {
                unsigned Lk = ls[k];
                unsigned peers = __match_any_sync(0xffffffffu, Lk);
                if (Lk && lane == (__ffs(peers) - 1)) {
                    unsigned n   = (unsigned)__popc(peers);
                    unsigned old = atomicAdd(&g_cnt[Lk], n);
                    unsigned long long key =
                        ((unsigned long long)(old + n) << 32) |
                        (unsigned long long)(0xFFFFFFFFu - Lk);
                    atomicMax(&blockKey, key);
                }
            }
        }
        __syncthreads();
        if (t == 0) g_pkey[b] = blockKey;
    }

    grid_barrier();

    // reduce keys
    unsigned long long kmax = 0ull;
    for (int i = t; i < NBF; i += NT) {
        unsigned long long kk = g_pkey[i];
        kmax = (kk > kmax) ? kk : kmax;
    }
    #pragma unroll
    for (int off = 16; off > 0; off >>= 1) {
        unsigned long long o = __shfl_down_sync(0xffffffffu, kmax, off);
        kmax = (o > kmax) ? o : kmax;
    }
    __shared__ unsigned long long shk[NT / 32];
    if (lane == 0) shk[wid] = kmax;
    __syncthreads();
    if (t == 0) {
        kmax = 0ull;
        #pragma unroll
        for (int w = 0; w < NT / 32; ++w)
            kmax = (shk[w] > kmax) ? shk[w] : kmax;
        bc_k = kmax;
    }
    __syncthreads();
    unsigned win = 0xFFFFFFFFu - (unsigned)(bc_k & 0xFFFFFFFFull);

    // overwrite speculative outputs with true component compare
    for (int q = b * NT + t; q < NQ; q += NBF * NT) {
        uint4 L = ((const uint4*)g_lab)[q];
        float4 nf = make_float4(L.x == win ? 1.f : 0.f, L.y == win ? 1.f : 0.f,
                                L.z == win ? 1.f : 0.f, L.w == win ? 1.f : 0.f);
        out[2 * NQ + q] = nf;                 // new_field
        if (st < 500) out[NQ + q] = nf;       // valid (st>=500 already correct)
        ((uint4*)g_cnt)[q] = make_uint4(0u, 0u, 0u, 0u);  // re-zero hist
    }
    if (b == 0 && t == 0) g_cnt[G3n] = 0u;
}

// ---------------------------------------------------------------------------
extern "C" void kernel_launch(void* const* d_in, const int* in_sizes, int n_in,
                              void* d_out, int out_size) {
    const float4* dens = (const float4*)d_in[0];
    const float4* cach = (const float4*)d_in[1];
    const int4*   oldf = (const int4*)d_in[2];
    const int*    step = (const int*)d_in[3];
    float4*       out  = (float4*)d_out;

    k_all<<<NBF, NT>>>(dens, cach, oldf, step, out);
}